// round 11
// baseline (speedup 1.0000x reference)
#include <cuda_runtime.h>
#include <cstdint>
#include <math.h>

#define Bn 32
#define Cn 224
#define Tn 2048
#define TT 32            // t-columns per stage-1 block
#define NW1 8            // warps per stage-1 block
#define CW 28            // channels per warp (8*28 = 224)
#define BC (Bn * Cn)     // 7168 sequences
#define PITCH 2304       // g_I row pitch in floats (2048 + 256 pad)
#define CHK 64           // stage-2 chunk (t-steps per ring stage)
#define SROW 68          // smem row stride in floats (64 + 4; 272B)
#define WPB 4            // stage-2 warps per block (one per SMSP!)

// Intermediate I in natural [seq][t(padded)] layout (from stage 1).
__device__ float g_I[(size_t)BC * PITCH];

#define CP_ASYNC16(dst, src) \
    asm volatile("cp.async.cg.shared.global [%0], [%1], 16;" :: "r"(dst), "l"(src) : "memory")
#define CP_COMMIT() asm volatile("cp.async.commit_group;" ::: "memory")
#define CP_WAIT1()  asm volatile("cp.async.wait_group 1;" ::: "memory")

#define BULK_S2G(gdst, ssrc, bytes) \
    asm volatile("cp.async.bulk.global.shared::cta.bulk_group [%0], [%1], %2;" \
                 :: "l"(gdst), "r"(ssrc), "r"(bytes) : "memory")
#define BULK_COMMIT() asm volatile("cp.async.bulk.commit_group;" ::: "memory")
#define BULK_WAIT0()  asm volatile("cp.async.bulk.wait_group 0;" ::: "memory")
#define FENCE_ASYNC() asm volatile("fence.proxy.async.shared::cta;" ::: "memory")

// ---------------------------------------------------------------------------
// Stage 1 (unchanged — measured 23.2us): per (b, 32-t-tile), 256 threads.
// ---------------------------------------------------------------------------
__global__ void __launch_bounds__(256) agss_stage1(const float* __restrict__ x,
                                                   const float* __restrict__ lw) {
    __shared__ float xs[Cn * 33];          // [c][t], stride 33 (conflict-free)
    __shared__ float lws[Cn];
    __shared__ float pdot[NW1][32];
    __shared__ float kern_s[13 * TT];

    const int tid  = threadIdx.x;
    const int lane = tid & 31;
    const int wid  = tid >> 5;
    const int b    = blockIdx.y;
    const int t0   = blockIdx.x * TT;
    const int cw0  = wid * CW;

    const float* xb = x + ((size_t)b * Cn) * Tn + t0;

    if (tid < Cn) lws[tid] = lw[tid];

    #pragma unroll
    for (int i = tid; i < Cn * 8; i += 256) {
        int c = i >> 3, j = i & 7;
        float4 v = *(const float4*)(xb + (size_t)c * Tn + 4 * j);
        float* p = xs + c * 33 + 4 * j;
        p[0] = v.x; p[1] = v.y; p[2] = v.z; p[3] = v.w;
    }
    __syncthreads();

    {
        float s = 0.f, k = 0.f;
        #pragma unroll
        for (int j = 0; j < CW; j++) {
            int c = cw0 + j;
            float p  = __fmul_rn(xs[c * 33 + lane], lws[c]);
            float y  = __fsub_rn(p, k);
            float t2 = __fadd_rn(s, y);
            k = __fsub_rn(__fsub_rn(t2, s), y);
            s = t2;
        }
        pdot[wid][lane] = __fadd_rn(s, k);
    }
    __syncthreads();

    if (tid < TT) {
        float s = pdot[0][tid];
        #pragma unroll
        for (int w = 1; w < NW1; w++) s = __fadd_rn(s, pdot[w][tid]);
        float w = __fadd_rn(5.2f, __fmul_rn(s, 9.6f));
        w = fminf(fmaxf(w, 0.4f), 10.0f);
        float invw = __fdiv_rn(1.0f, w);

        float kern[13];
        #pragma unroll
        for (int k = 0; k < 13; k++) {
            float q = __fmul_rn((float)(k - 6), invw);
            kern[k] = expf(__fmul_rn(-0.5f, __fmul_rn(q, q)));
        }
        float q0 = __fmul_rn(0.93023255813953487f, invw);   // (120/129)/w
        float a  = __fmul_rn(0.5f, __fmul_rn(q0, q0));
        float rho  = expf(__fmul_rn(-2.0f, a));
        float term = expf(__fmul_rn(-0.25f, a));
        float ssum = term, qq = rho;
        #pragma unroll 8
        for (int m = 0; m < 64; m++) {
            term = __fmul_rn(term, qq);
            ssum = __fadd_rn(ssum, term);
            qq   = __fmul_rn(qq, rho);
        }
        float invn = __fdiv_rn(1.0f, __fmul_rn(2.0f, ssum));
        #pragma unroll
        for (int k = 0; k < 13; k++)
            kern_s[k * TT + tid] = __fmul_rn(kern[k], invn);
    }
    __syncthreads();

    float kk[13];
    #pragma unroll
    for (int k = 0; k < 13; k++) kk[k] = kern_s[k * TT + lane];

    float win[13];
    #pragma unroll
    for (int i = 0; i < 13; i++) {
        int c = cw0 - 6 + i;
        win[i] = (c >= 0 && c < Cn) ? xs[c * 33 + lane] : 0.0f;
    }

    float* Ib = g_I + ((size_t)b * Cn + cw0) * PITCH + t0 + lane;
    #pragma unroll
    for (int j = 0; j < CW; j++) {
        float acc = __fmul_rn(win[j % 13], kk[0]);
        #pragma unroll
        for (int i = 1; i < 13; i++)
            acc = fmaf(win[(j + i) % 13], kk[i], acc);
        float xc = win[(j + 6) % 13];
        float I  = __fsub_rn(xc, fmaxf(__fsub_rn(xc, acc), 0.0f));
        Ib[(size_t)j * PITCH] = I;
        int cn = cw0 + j + 7;
        win[j % 13] = (cn < Cn) ? xs[cn * 33 + lane] : 0.0f;
    }
}

// ---------------------------------------------------------------------------
// Stage 2: LIF scan. 56 blocks x 4 warps — warps land on SMSPs 0..3 (wid%4),
// one block per SM, single wave. Each warp owns 32 sequences + private smem
// slices + private cp.async / bulk groups; warp-local sync only.
//   in : warp-cooperative cp.async (row-major, coalesced) -> 3-stage ring
//   mid: LDS.128 double-buffered, FSET spike, STS.128 into otile
//   out: 32 x 256B cp.async.bulk shared->global (lane 0), wait0 at chunk start
// Exact reference op order per step: mem = (0.95*mem + v) - spk_prev.
// ---------------------------------------------------------------------------
__global__ void __launch_bounds__(32 * WPB) agss_stage2(float* __restrict__ out) {
    __shared__ __align__(16) float stile[WPB][3][32 * SROW];   // 4 x 26.1KB
    __shared__ __align__(16) float otile[WPB][32 * SROW];      // 4 x 8.7KB

    const int lane = threadIdx.x & 31;
    const int wid  = threadIdx.x >> 5;
    const int seq0 = blockIdx.x * (32 * WPB) + wid * 32;
    const float* gbase = g_I + (size_t)seq0 * PITCH;

    unsigned int sb = (unsigned int)__cvta_generic_to_shared(&stile[wid][0][0]);
    unsigned int ob = (unsigned int)__cvta_generic_to_shared(&otile[wid][0]);

    // lane covers 16B of row (r + lane>>4): 16 lanes span one 256B row
    const int rsub = lane >> 4;             // 0 or 1
    const int csub = (lane & 15) * 4;       // 0..60
    const unsigned int dlane = sb + (unsigned int)((rsub * SROW + csub) * 4);
    const float* glane = gbase + (size_t)rsub * PITCH + csub;

    // prefetch chunks 0 and 1 into stages 0, 1
    #pragma unroll
    for (int k = 0; k < 2; k++) {
        unsigned int d = dlane + (unsigned int)(k * 32 * SROW * 4);
        const float* g = glane + k * CHK;
        #pragma unroll
        for (int r = 0; r < 32; r += 2)
            CP_ASYNC16(d + (unsigned int)(r * SROW * 4), g + (size_t)r * PITCH);
        CP_COMMIT();
    }

    float mem = 0.0f, spf = 0.0f;
    float o0, o1, o2;

    #pragma unroll 1
    for (int k = 0; k < Tn / CHK; k++) {
        CP_WAIT1();                 // input chunk k landed
        BULK_WAIT0();               // otile free (lane 0's bulk drained)
        __syncwarp();

        const float* st = &stile[wid][0][0] + (k % 3) * (32 * SROW) + lane * SROW;
        float* otp = &otile[wid][0] + lane * SROW;

        float4 v = *(const float4*)(st);
        #pragma unroll
        for (int i4 = 0; i4 < CHK; i4 += 4) {
            float4 vn;
            if (i4 + 4 < CHK) vn = *(const float4*)(st + i4 + 4);
            float q;
            q = __fadd_rn(__fmul_rn(0.95f, mem), v.x);
            mem = __fsub_rn(q, spf);
            asm("set.gt.f32.f32 %0, %1, %2;" : "=f"(spf) : "f"(mem), "f"(1.0f));
            o0 = spf;
            q = __fadd_rn(__fmul_rn(0.95f, mem), v.y);
            mem = __fsub_rn(q, spf);
            asm("set.gt.f32.f32 %0, %1, %2;" : "=f"(spf) : "f"(mem), "f"(1.0f));
            o1 = spf;
            q = __fadd_rn(__fmul_rn(0.95f, mem), v.z);
            mem = __fsub_rn(q, spf);
            asm("set.gt.f32.f32 %0, %1, %2;" : "=f"(spf) : "f"(mem), "f"(1.0f));
            o2 = spf;
            q = __fadd_rn(__fmul_rn(0.95f, mem), v.w);
            mem = __fsub_rn(q, spf);
            asm("set.gt.f32.f32 %0, %1, %2;" : "=f"(spf) : "f"(mem), "f"(1.0f));
            *(float4*)(otp + i4) = make_float4(o0, o1, o2, spf);
            v = vn;
        }

        // prefetch input chunk k+2 (row pad keeps loads in-bounds)
        {
            unsigned int d = dlane + (unsigned int)(((k + 2) % 3) * 32 * SROW * 4);
            const float* g = glane + (k + 2) * CHK;
            #pragma unroll
            for (int r = 0; r < 32; r += 2)
                CP_ASYNC16(d + (unsigned int)(r * SROW * 4), g + (size_t)r * PITCH);
            CP_COMMIT();
        }

        __syncwarp();               // all lanes' STS to otile visible
        if (lane == 0) {
            FENCE_ASYNC();          // order STS -> async proxy
            #pragma unroll
            for (int r = 0; r < 32; r++) {
                float* gd = out + (size_t)(seq0 + r) * Tn + k * CHK;
                unsigned int ss = ob + (unsigned int)(r * SROW * 4);
                BULK_S2G(gd, ss, CHK * 4);
            }
            BULK_COMMIT();
        }
        __syncwarp();
    }
    BULK_WAIT0();                   // drain last chunk's bulk stores
}

// ---------------------------------------------------------------------------
extern "C" void kernel_launch(void* const* d_in, const int* in_sizes, int n_in,
                              void* d_out, int out_size) {
    const float* inp = (const float*)d_in[0];   // (32,1,224,2048) f32
    const float* lw  = (const float*)d_in[1];   // (1,224) f32
    float* out = (float*)d_out;                 // (32,1,224,2048) f32

    dim3 g1(Tn / TT, Bn);
    agss_stage1<<<g1, 256>>>(inp, lw);
    agss_stage2<<<BC / (32 * WPB), 32 * WPB>>>(out);
}

// round 12
// speedup vs baseline: 1.3511x; 1.3511x over previous
#include <cuda_runtime.h>
#include <cstdint>
#include <math.h>

#define Bn 32
#define Cn 224
#define Tn 2048
#define TT 32            // t-columns per stage-1 block
#define NW1 8            // warps per stage-1 block
#define CW 28            // channels per warp (8*28 = 224)
#define BC (Bn * Cn)     // 7168 sequences
#define PITCH 2304       // g_I row pitch in floats (2048 + 256 pad)
#define CHK 128          // stage-2 chunk (t-steps per ring stage)
#define SROW 132         // smem row stride in floats (128 + 4)
#define WPB 2            // stage-2 warps per block (SMSP 0 and 1; 112 blocks = 1/SM)

// Intermediate I in natural [seq][t(padded)] layout (from stage 1).
__device__ float g_I[(size_t)BC * PITCH];

#define CP_ASYNC16(dst, src) \
    asm volatile("cp.async.cg.shared.global [%0], [%1], 16;" :: "r"(dst), "l"(src) : "memory")
#define CP_COMMIT() asm volatile("cp.async.commit_group;" ::: "memory")
#define CP_WAIT1()  asm volatile("cp.async.wait_group 1;" ::: "memory")

#define BULK_S2G(gdst, ssrc, bytes) \
    asm volatile("cp.async.bulk.global.shared::cta.bulk_group [%0], [%1], %2;" \
                 :: "l"(gdst), "r"(ssrc), "r"(bytes) : "memory")
#define BULK_COMMIT() asm volatile("cp.async.bulk.commit_group;" ::: "memory")
#define BULK_WAIT1()  asm volatile("cp.async.bulk.wait_group 1;" ::: "memory")
#define BULK_WAIT0()  asm volatile("cp.async.bulk.wait_group 0;" ::: "memory")
#define FENCE_ASYNC() asm volatile("fence.proxy.async.shared::cta;" ::: "memory")

// ---------------------------------------------------------------------------
// Stage 1 (unchanged — measured 23.2us): per (b, 32-t-tile), 256 threads.
// ---------------------------------------------------------------------------
__global__ void __launch_bounds__(256) agss_stage1(const float* __restrict__ x,
                                                   const float* __restrict__ lw) {
    __shared__ float xs[Cn * 33];          // [c][t], stride 33 (conflict-free)
    __shared__ float lws[Cn];
    __shared__ float pdot[NW1][32];
    __shared__ float kern_s[13 * TT];

    const int tid  = threadIdx.x;
    const int lane = tid & 31;
    const int wid  = tid >> 5;
    const int b    = blockIdx.y;
    const int t0   = blockIdx.x * TT;
    const int cw0  = wid * CW;

    const float* xb = x + ((size_t)b * Cn) * Tn + t0;

    if (tid < Cn) lws[tid] = lw[tid];

    #pragma unroll
    for (int i = tid; i < Cn * 8; i += 256) {
        int c = i >> 3, j = i & 7;
        float4 v = *(const float4*)(xb + (size_t)c * Tn + 4 * j);
        float* p = xs + c * 33 + 4 * j;
        p[0] = v.x; p[1] = v.y; p[2] = v.z; p[3] = v.w;
    }
    __syncthreads();

    {
        float s = 0.f, k = 0.f;
        #pragma unroll
        for (int j = 0; j < CW; j++) {
            int c = cw0 + j;
            float p  = __fmul_rn(xs[c * 33 + lane], lws[c]);
            float y  = __fsub_rn(p, k);
            float t2 = __fadd_rn(s, y);
            k = __fsub_rn(__fsub_rn(t2, s), y);
            s = t2;
        }
        pdot[wid][lane] = __fadd_rn(s, k);
    }
    __syncthreads();

    if (tid < TT) {
        float s = pdot[0][tid];
        #pragma unroll
        for (int w = 1; w < NW1; w++) s = __fadd_rn(s, pdot[w][tid]);
        float w = __fadd_rn(5.2f, __fmul_rn(s, 9.6f));
        w = fminf(fmaxf(w, 0.4f), 10.0f);
        float invw = __fdiv_rn(1.0f, w);

        float kern[13];
        #pragma unroll
        for (int k = 0; k < 13; k++) {
            float q = __fmul_rn((float)(k - 6), invw);
            kern[k] = expf(__fmul_rn(-0.5f, __fmul_rn(q, q)));
        }
        float q0 = __fmul_rn(0.93023255813953487f, invw);   // (120/129)/w
        float a  = __fmul_rn(0.5f, __fmul_rn(q0, q0));
        float rho  = expf(__fmul_rn(-2.0f, a));
        float term = expf(__fmul_rn(-0.25f, a));
        float ssum = term, qq = rho;
        #pragma unroll 8
        for (int m = 0; m < 64; m++) {
            term = __fmul_rn(term, qq);
            ssum = __fadd_rn(ssum, term);
            qq   = __fmul_rn(qq, rho);
        }
        float invn = __fdiv_rn(1.0f, __fmul_rn(2.0f, ssum));
        #pragma unroll
        for (int k = 0; k < 13; k++)
            kern_s[k * TT + tid] = __fmul_rn(kern[k], invn);
    }
    __syncthreads();

    float kk[13];
    #pragma unroll
    for (int k = 0; k < 13; k++) kk[k] = kern_s[k * TT + lane];

    float win[13];
    #pragma unroll
    for (int i = 0; i < 13; i++) {
        int c = cw0 - 6 + i;
        win[i] = (c >= 0 && c < Cn) ? xs[c * 33 + lane] : 0.0f;
    }

    float* Ib = g_I + ((size_t)b * Cn + cw0) * PITCH + t0 + lane;
    #pragma unroll
    for (int j = 0; j < CW; j++) {
        float acc = __fmul_rn(win[j % 13], kk[0]);
        #pragma unroll
        for (int i = 1; i < 13; i++)
            acc = fmaf(win[(j + i) % 13], kk[i], acc);
        float xc = win[(j + 6) % 13];
        float I  = __fsub_rn(xc, fmaxf(__fsub_rn(xc, acc), 0.0f));
        Ib[(size_t)j * PITCH] = I;
        int cn = cw0 + j + 7;
        win[j % 13] = (cn < Cn) ? xs[cn * 33 + lane] : 0.0f;
    }
}

// ---------------------------------------------------------------------------
// Stage 2: LIF scan. R10's proven per-warp pipeline (CHK=128, 3-stage input
// ring, DOUBLE-buffered otile with BULK_WAIT1), packed 2 warps per block:
// 112 blocks = one per SM (single wave), warp 0 -> SMSP0, warp 1 -> SMSP1 —
// eliminates the 2-blocks-on-SMSP0 collision that doubled R10's tail.
// Per-warp: private smem slices, private cp.async/bulk groups, warp syncs.
// Exact reference op order per step: mem = (0.95*mem + v) - spk_prev.
// ---------------------------------------------------------------------------
__global__ void __launch_bounds__(32 * WPB) agss_stage2(float* __restrict__ out) {
    __shared__ __align__(16) float stile[WPB][3][32 * SROW];   // 2 x 50.7KB
    __shared__ __align__(16) float otile[WPB][2][32 * SROW];   // 2 x 33.8KB

    const int lane = threadIdx.x & 31;
    const int wid  = threadIdx.x >> 5;
    const int seq0 = blockIdx.x * (32 * WPB) + wid * 32;
    const float* gbase = g_I + (size_t)seq0 * PITCH;

    unsigned int sb = (unsigned int)__cvta_generic_to_shared(&stile[wid][0][0]);
    unsigned int ob = (unsigned int)__cvta_generic_to_shared(&otile[wid][0][0]);

    // prefetch chunks 0 and 1: lane covers 16B of row r (row-major, coalesced)
    #pragma unroll
    for (int k = 0; k < 2; k++) {
        #pragma unroll
        for (int r = 0; r < 32; r++) {
            unsigned int d = sb + (unsigned int)((k * 32 * SROW + r * SROW + 4 * lane) * 4);
            const float* g = gbase + (size_t)r * PITCH + k * CHK + 4 * lane;
            CP_ASYNC16(d, g);
        }
        CP_COMMIT();
    }

    float mem = 0.0f, spf = 0.0f;
    float o0, o1, o2;

    #pragma unroll 1
    for (int k = 0; k < Tn / CHK; k++) {
        CP_WAIT1();                 // input chunk k landed
        BULK_WAIT1();               // otile[k&1] free (chunk k-2's copies done)
        __syncwarp();

        const float* st = &stile[wid][0][0] + (k % 3) * (32 * SROW) + lane * SROW;
        float* otp = &otile[wid][0][0] + (k & 1) * (32 * SROW) + lane * SROW;

        float4 v = *(const float4*)(st);
        #pragma unroll
        for (int i4 = 0; i4 < CHK; i4 += 4) {
            float4 vn;
            if (i4 + 4 < CHK) vn = *(const float4*)(st + i4 + 4);  // next buffer
            float q;
            q = __fadd_rn(__fmul_rn(0.95f, mem), v.x);
            mem = __fsub_rn(q, spf);
            asm("set.gt.f32.f32 %0, %1, %2;" : "=f"(spf) : "f"(mem), "f"(1.0f));
            o0 = spf;
            q = __fadd_rn(__fmul_rn(0.95f, mem), v.y);
            mem = __fsub_rn(q, spf);
            asm("set.gt.f32.f32 %0, %1, %2;" : "=f"(spf) : "f"(mem), "f"(1.0f));
            o1 = spf;
            q = __fadd_rn(__fmul_rn(0.95f, mem), v.z);
            mem = __fsub_rn(q, spf);
            asm("set.gt.f32.f32 %0, %1, %2;" : "=f"(spf) : "f"(mem), "f"(1.0f));
            o2 = spf;
            q = __fadd_rn(__fmul_rn(0.95f, mem), v.w);
            mem = __fsub_rn(q, spf);
            asm("set.gt.f32.f32 %0, %1, %2;" : "=f"(spf) : "f"(mem), "f"(1.0f));
            *(float4*)(otp + i4) = make_float4(o0, o1, o2, spf);
            v = vn;
        }

        // prefetch input chunk k+2 (row pad keeps loads in-bounds)
        #pragma unroll
        for (int r = 0; r < 32; r++) {
            unsigned int d = sb + (unsigned int)((((k + 2) % 3) * 32 * SROW
                                + r * SROW + 4 * lane) * 4);
            const float* g = gbase + (size_t)r * PITCH + (k + 2) * CHK + 4 * lane;
            CP_ASYNC16(d, g);
        }
        CP_COMMIT();

        __syncwarp();               // all lanes' STS to otile visible
        if (lane == 0) {
            FENCE_ASYNC();          // order STS -> async proxy
            #pragma unroll
            for (int r = 0; r < 32; r++) {
                float* gd = out + (size_t)(seq0 + r) * Tn + k * CHK;
                unsigned int ss = ob + (unsigned int)(((k & 1) * 32 * SROW + r * SROW) * 4);
                BULK_S2G(gd, ss, CHK * 4);
            }
            BULK_COMMIT();
        }
        __syncwarp();
    }
    BULK_WAIT0();                   // drain outstanding bulk stores
}

// ---------------------------------------------------------------------------
extern "C" void kernel_launch(void* const* d_in, const int* in_sizes, int n_in,
                              void* d_out, int out_size) {
    const float* inp = (const float*)d_in[0];   // (32,1,224,2048) f32
    const float* lw  = (const float*)d_in[1];   // (1,224) f32
    float* out = (float*)d_out;                 // (32,1,224,2048) f32

    dim3 g1(Tn / TT, Bn);
    agss_stage1<<<g1, 256>>>(inp, lw);
    agss_stage2<<<BC / (32 * WPB), 32 * WPB>>>(out);
}

// round 13
// speedup vs baseline: 1.6347x; 1.2099x over previous
#include <cuda_runtime.h>
#include <cstdint>
#include <math.h>

#define Bn 32
#define Cn 224
#define Tn 2048
#define TT 32            // t-columns per stage-1 block
#define NW1 8            // warps per stage-1 block
#define CW 28            // channels per warp (8*28 = 224)
#define BC (Bn * Cn)     // 7168 sequences
#define PITCH 2304       // g_I row pitch in floats (2048 + 256 pad)
#define CHK 128          // stage-2 chunk (t-steps per ring stage)
#define SROW 132         // smem row stride in floats (128 + 4)

// Intermediate I in natural [seq][t(padded)] layout (from stage 1).
__device__ float g_I[(size_t)BC * PITCH];

#define CP_ASYNC16(dst, src) \
    asm volatile("cp.async.cg.shared.global [%0], [%1], 16;" :: "r"(dst), "l"(src) : "memory")
#define CP_COMMIT() asm volatile("cp.async.commit_group;" ::: "memory")
#define CP_WAIT1()  asm volatile("cp.async.wait_group 1;" ::: "memory")

#define BULK_S2G(gdst, ssrc, bytes) \
    asm volatile("cp.async.bulk.global.shared::cta.bulk_group [%0], [%1], %2;" \
                 :: "l"(gdst), "r"(ssrc), "r"(bytes) : "memory")
#define BULK_COMMIT() asm volatile("cp.async.bulk.commit_group;" ::: "memory")
#define BULK_WAIT1()  asm volatile("cp.async.bulk.wait_group 1;" ::: "memory")
#define BULK_WAIT0()  asm volatile("cp.async.bulk.wait_group 0;" ::: "memory")
#define FENCE_ASYNC() asm volatile("fence.proxy.async.shared::cta;" ::: "memory")

// ---------------------------------------------------------------------------
// Stage 1 (unchanged — measured 23.2us): per (b, 32-t-tile), 256 threads.
// ---------------------------------------------------------------------------
__global__ void __launch_bounds__(256) agss_stage1(const float* __restrict__ x,
                                                   const float* __restrict__ lw) {
    __shared__ float xs[Cn * 33];          // [c][t], stride 33 (conflict-free)
    __shared__ float lws[Cn];
    __shared__ float pdot[NW1][32];
    __shared__ float kern_s[13 * TT];

    const int tid  = threadIdx.x;
    const int lane = tid & 31;
    const int wid  = tid >> 5;
    const int b    = blockIdx.y;
    const int t0   = blockIdx.x * TT;
    const int cw0  = wid * CW;

    const float* xb = x + ((size_t)b * Cn) * Tn + t0;

    if (tid < Cn) lws[tid] = lw[tid];

    #pragma unroll
    for (int i = tid; i < Cn * 8; i += 256) {
        int c = i >> 3, j = i & 7;
        float4 v = *(const float4*)(xb + (size_t)c * Tn + 4 * j);
        float* p = xs + c * 33 + 4 * j;
        p[0] = v.x; p[1] = v.y; p[2] = v.z; p[3] = v.w;
    }
    __syncthreads();

    {
        float s = 0.f, k = 0.f;
        #pragma unroll
        for (int j = 0; j < CW; j++) {
            int c = cw0 + j;
            float p  = __fmul_rn(xs[c * 33 + lane], lws[c]);
            float y  = __fsub_rn(p, k);
            float t2 = __fadd_rn(s, y);
            k = __fsub_rn(__fsub_rn(t2, s), y);
            s = t2;
        }
        pdot[wid][lane] = __fadd_rn(s, k);
    }
    __syncthreads();

    if (tid < TT) {
        float s = pdot[0][tid];
        #pragma unroll
        for (int w = 1; w < NW1; w++) s = __fadd_rn(s, pdot[w][tid]);
        float w = __fadd_rn(5.2f, __fmul_rn(s, 9.6f));
        w = fminf(fmaxf(w, 0.4f), 10.0f);
        float invw = __fdiv_rn(1.0f, w);

        float kern[13];
        #pragma unroll
        for (int k = 0; k < 13; k++) {
            float q = __fmul_rn((float)(k - 6), invw);
            kern[k] = expf(__fmul_rn(-0.5f, __fmul_rn(q, q)));
        }
        float q0 = __fmul_rn(0.93023255813953487f, invw);   // (120/129)/w
        float a  = __fmul_rn(0.5f, __fmul_rn(q0, q0));
        float rho  = expf(__fmul_rn(-2.0f, a));
        float term = expf(__fmul_rn(-0.25f, a));
        float ssum = term, qq = rho;
        #pragma unroll 8
        for (int m = 0; m < 64; m++) {
            term = __fmul_rn(term, qq);
            ssum = __fadd_rn(ssum, term);
            qq   = __fmul_rn(qq, rho);
        }
        float invn = __fdiv_rn(1.0f, __fmul_rn(2.0f, ssum));
        #pragma unroll
        for (int k = 0; k < 13; k++)
            kern_s[k * TT + tid] = __fmul_rn(kern[k], invn);
    }
    __syncthreads();

    float kk[13];
    #pragma unroll
    for (int k = 0; k < 13; k++) kk[k] = kern_s[k * TT + lane];

    float win[13];
    #pragma unroll
    for (int i = 0; i < 13; i++) {
        int c = cw0 - 6 + i;
        win[i] = (c >= 0 && c < Cn) ? xs[c * 33 + lane] : 0.0f;
    }

    float* Ib = g_I + ((size_t)b * Cn + cw0) * PITCH + t0 + lane;
    #pragma unroll
    for (int j = 0; j < CW; j++) {
        float acc = __fmul_rn(win[j % 13], kk[0]);
        #pragma unroll
        for (int i = 1; i < 13; i++)
            acc = fmaf(win[(j + i) % 13], kk[i], acc);
        float xc = win[(j + 6) % 13];
        float I  = __fsub_rn(xc, fmaxf(__fsub_rn(xc, acc), 0.0f));
        Ib[(size_t)j * PITCH] = I;
        int cn = cw0 + j + 7;
        win[j % 13] = (cn < Cn) ? xs[cn * 33 + lane] : 0.0f;
    }
}

// ---------------------------------------------------------------------------
// Stage 2: R10's proven single-warp pipeline, UNCHANGED hot path (regs ~69),
// but launched as 224 blocks x 64 threads with ONE active warp per block:
//   bid < 148  -> warp 0 active (SMSP 0)
//   bid >= 148 -> warp 1 active (SMSP 1)
// Classic placement co-locates bids b and b+148 on the same SM; with 84KB
// static smem exactly 2 blocks co-reside -> the colliding pair now occupies
// SMSP0 + SMSP1 instead of both fighting for SMSP0.
// ---------------------------------------------------------------------------
__global__ void __launch_bounds__(64) agss_stage2(float* __restrict__ out) {
    __shared__ __align__(16) float stile[3][32 * SROW];   // input ring (50.7KB)
    __shared__ __align__(16) float otile[2][32 * SROW];   // output bufs (33.8KB)

    const int wsel = (blockIdx.x < 148) ? 0 : 1;          // SMSP disambiguation
    if ((threadIdx.x >> 5) != wsel) return;               // other warp exits

    const int lane = threadIdx.x & 31;
    const int seq0 = blockIdx.x * 32;
    const float* gbase = g_I + (size_t)seq0 * PITCH;

    unsigned int sb = (unsigned int)__cvta_generic_to_shared(&stile[0][0]);
    unsigned int ob = (unsigned int)__cvta_generic_to_shared(&otile[0][0]);

    // prefetch chunks 0 and 1: lane covers 16B of row r (row-major, coalesced)
    #pragma unroll
    for (int k = 0; k < 2; k++) {
        #pragma unroll
        for (int r = 0; r < 32; r++) {
            unsigned int d = sb + (unsigned int)((k * 32 * SROW + r * SROW + 4 * lane) * 4);
            const float* g = gbase + (size_t)r * PITCH + k * CHK + 4 * lane;
            CP_ASYNC16(d, g);
        }
        CP_COMMIT();
    }

    float mem = 0.0f, spf = 0.0f;
    float o0, o1, o2;

    #pragma unroll 1
    for (int k = 0; k < Tn / CHK; k++) {
        CP_WAIT1();                 // input chunk k landed
        BULK_WAIT1();               // otile[k&1] free (chunk k-2's copies done)
        __syncwarp();

        const float* st = &stile[0][0] + (k % 3) * (32 * SROW) + lane * SROW;
        float* otp = &otile[0][0] + (k & 1) * (32 * SROW) + lane * SROW;

        float4 v = *(const float4*)(st);
        #pragma unroll
        for (int i4 = 0; i4 < CHK; i4 += 4) {
            float4 vn;
            if (i4 + 4 < CHK) vn = *(const float4*)(st + i4 + 4);  // next buffer
            float q;
            q = __fadd_rn(__fmul_rn(0.95f, mem), v.x);
            mem = __fsub_rn(q, spf);
            asm("set.gt.f32.f32 %0, %1, %2;" : "=f"(spf) : "f"(mem), "f"(1.0f));
            o0 = spf;
            q = __fadd_rn(__fmul_rn(0.95f, mem), v.y);
            mem = __fsub_rn(q, spf);
            asm("set.gt.f32.f32 %0, %1, %2;" : "=f"(spf) : "f"(mem), "f"(1.0f));
            o1 = spf;
            q = __fadd_rn(__fmul_rn(0.95f, mem), v.z);
            mem = __fsub_rn(q, spf);
            asm("set.gt.f32.f32 %0, %1, %2;" : "=f"(spf) : "f"(mem), "f"(1.0f));
            o2 = spf;
            q = __fadd_rn(__fmul_rn(0.95f, mem), v.w);
            mem = __fsub_rn(q, spf);
            asm("set.gt.f32.f32 %0, %1, %2;" : "=f"(spf) : "f"(mem), "f"(1.0f));
            *(float4*)(otp + i4) = make_float4(o0, o1, o2, spf);
            v = vn;
        }

        // prefetch input chunk k+2 (row pad keeps loads in-bounds)
        #pragma unroll
        for (int r = 0; r < 32; r++) {
            unsigned int d = sb + (unsigned int)((((k + 2) % 3) * 32 * SROW
                                + r * SROW + 4 * lane) * 4);
            const float* g = gbase + (size_t)r * PITCH + (k + 2) * CHK + 4 * lane;
            CP_ASYNC16(d, g);
        }
        CP_COMMIT();

        __syncwarp();               // all lanes' STS to otile visible
        if (lane == 0) {
            FENCE_ASYNC();          // order STS -> async proxy
            #pragma unroll
            for (int r = 0; r < 32; r++) {
                float* gd = out + (size_t)(seq0 + r) * Tn + k * CHK;
                unsigned int ss = ob + (unsigned int)(((k & 1) * 32 * SROW + r * SROW) * 4);
                BULK_S2G(gd, ss, CHK * 4);
            }
            BULK_COMMIT();
        }
        __syncwarp();
    }
    BULK_WAIT0();                   // drain outstanding bulk stores
}

// ---------------------------------------------------------------------------
extern "C" void kernel_launch(void* const* d_in, const int* in_sizes, int n_in,
                              void* d_out, int out_size) {
    const float* inp = (const float*)d_in[0];   // (32,1,224,2048) f32
    const float* lw  = (const float*)d_in[1];   // (1,224) f32
    float* out = (float*)d_out;                 // (32,1,224,2048) f32

    dim3 g1(Tn / TT, Bn);
    agss_stage1<<<g1, 256>>>(inp, lw);
    agss_stage2<<<BC / 32, 64>>>(out);
}

// round 14
// speedup vs baseline: 1.6384x; 1.0022x over previous
#include <cuda_runtime.h>
#include <cstdint>
#include <math.h>

#define Bn 32
#define Cn 224
#define Tn 2048
#define TT 32            // t-columns per stage-1 block
#define NW1 8            // warps per stage-1 block
#define CW 28            // channels per warp (8*28 = 224)
#define BC (Bn * Cn)     // 7168 sequences
#define PITCH 2304       // g_I row pitch in floats (2048 + 256 pad)
#define CHK 128          // stage-2 chunk (t-steps per ring stage)
#define SROW 132         // smem row stride in floats (128 + 4)

// Intermediate I in natural [seq][t(padded)] layout (from stage 1).
__device__ float g_I[(size_t)BC * PITCH];

#define CP_ASYNC16(dst, src) \
    asm volatile("cp.async.cg.shared.global [%0], [%1], 16;" :: "r"(dst), "l"(src) : "memory")
#define CP_COMMIT() asm volatile("cp.async.commit_group;" ::: "memory")
#define CP_WAIT1()  asm volatile("cp.async.wait_group 1;" ::: "memory")

#define BULK_S2G(gdst, ssrc, bytes) \
    asm volatile("cp.async.bulk.global.shared::cta.bulk_group [%0], [%1], %2;" \
                 :: "l"(gdst), "r"(ssrc), "r"(bytes) : "memory")
#define BULK_COMMIT() asm volatile("cp.async.bulk.commit_group;" ::: "memory")
#define BULK_WAIT1()  asm volatile("cp.async.bulk.wait_group 1;" ::: "memory")
#define BULK_WAIT0()  asm volatile("cp.async.bulk.wait_group 0;" ::: "memory")
#define FENCE_ASYNC() asm volatile("fence.proxy.async.shared::cta;" ::: "memory")

// Exact spike: spf = sat((mem - 1) * 2^46) == (mem > 1 ? 1.0f : 0.0f).
// Single FFMA.SAT, latency 4 — replaces FSETP(13)+SEL(4) on the loop chain.
#define SPIKE(spf, mem, c1, c2) \
    asm("fma.rn.sat.f32 %0, %1, %2, %3;" : "=f"(spf) : "f"(mem), "f"(c1), "f"(c2))

// ---------------------------------------------------------------------------
// Stage 1 (unchanged — measured 23.2us): per (b, 32-t-tile), 256 threads.
// ---------------------------------------------------------------------------
__global__ void __launch_bounds__(256) agss_stage1(const float* __restrict__ x,
                                                   const float* __restrict__ lw) {
    __shared__ float xs[Cn * 33];          // [c][t], stride 33 (conflict-free)
    __shared__ float lws[Cn];
    __shared__ float pdot[NW1][32];
    __shared__ float kern_s[13 * TT];

    const int tid  = threadIdx.x;
    const int lane = tid & 31;
    const int wid  = tid >> 5;
    const int b    = blockIdx.y;
    const int t0   = blockIdx.x * TT;
    const int cw0  = wid * CW;

    const float* xb = x + ((size_t)b * Cn) * Tn + t0;

    if (tid < Cn) lws[tid] = lw[tid];

    #pragma unroll
    for (int i = tid; i < Cn * 8; i += 256) {
        int c = i >> 3, j = i & 7;
        float4 v = *(const float4*)(xb + (size_t)c * Tn + 4 * j);
        float* p = xs + c * 33 + 4 * j;
        p[0] = v.x; p[1] = v.y; p[2] = v.z; p[3] = v.w;
    }
    __syncthreads();

    {
        float s = 0.f, k = 0.f;
        #pragma unroll
        for (int j = 0; j < CW; j++) {
            int c = cw0 + j;
            float p  = __fmul_rn(xs[c * 33 + lane], lws[c]);
            float y  = __fsub_rn(p, k);
            float t2 = __fadd_rn(s, y);
            k = __fsub_rn(__fsub_rn(t2, s), y);
            s = t2;
        }
        pdot[wid][lane] = __fadd_rn(s, k);
    }
    __syncthreads();

    if (tid < TT) {
        float s = pdot[0][tid];
        #pragma unroll
        for (int w = 1; w < NW1; w++) s = __fadd_rn(s, pdot[w][tid]);
        float w = __fadd_rn(5.2f, __fmul_rn(s, 9.6f));
        w = fminf(fmaxf(w, 0.4f), 10.0f);
        float invw = __fdiv_rn(1.0f, w);

        float kern[13];
        #pragma unroll
        for (int k = 0; k < 13; k++) {
            float q = __fmul_rn((float)(k - 6), invw);
            kern[k] = expf(__fmul_rn(-0.5f, __fmul_rn(q, q)));
        }
        float q0 = __fmul_rn(0.93023255813953487f, invw);   // (120/129)/w
        float a  = __fmul_rn(0.5f, __fmul_rn(q0, q0));
        float rho  = expf(__fmul_rn(-2.0f, a));
        float term = expf(__fmul_rn(-0.25f, a));
        float ssum = term, qq = rho;
        #pragma unroll 8
        for (int m = 0; m < 64; m++) {
            term = __fmul_rn(term, qq);
            ssum = __fadd_rn(ssum, term);
            qq   = __fmul_rn(qq, rho);
        }
        float invn = __fdiv_rn(1.0f, __fmul_rn(2.0f, ssum));
        #pragma unroll
        for (int k = 0; k < 13; k++)
            kern_s[k * TT + tid] = __fmul_rn(kern[k], invn);
    }
    __syncthreads();

    float kk[13];
    #pragma unroll
    for (int k = 0; k < 13; k++) kk[k] = kern_s[k * TT + lane];

    float win[13];
    #pragma unroll
    for (int i = 0; i < 13; i++) {
        int c = cw0 - 6 + i;
        win[i] = (c >= 0 && c < Cn) ? xs[c * 33 + lane] : 0.0f;
    }

    float* Ib = g_I + ((size_t)b * Cn + cw0) * PITCH + t0 + lane;
    #pragma unroll
    for (int j = 0; j < CW; j++) {
        float acc = __fmul_rn(win[j % 13], kk[0]);
        #pragma unroll
        for (int i = 1; i < 13; i++)
            acc = fmaf(win[(j + i) % 13], kk[i], acc);
        float xc = win[(j + 6) % 13];
        float I  = __fsub_rn(xc, fmaxf(__fsub_rn(xc, acc), 0.0f));
        Ib[(size_t)j * PITCH] = I;
        int cn = cw0 + j + 7;
        win[j % 13] = (cn < Cn) ? xs[cn * 33 + lane] : 0.0f;
    }
}

// ---------------------------------------------------------------------------
// Stage 2: LIF scan — R13 structure, spike via single FFMA.SAT (lat 4),
// removing the FSETP(13)+SEL(4) predicate path from the loop-carried chain:
//   mem -> FFMA.SAT -> spf (@4)  ||  mem -> FMUL -> FADD -> q (@8)
//   FSUB(q, spf) -> mem' (@12)          ==> period ~12 cyc/step.
// Exact: sat((mem-1)*2^46) == (mem > 1) ? 1.0f : 0.0f for all attainable mem.
// ---------------------------------------------------------------------------
__global__ void __launch_bounds__(64) agss_stage2(float* __restrict__ out) {
    __shared__ __align__(16) float stile[3][32 * SROW];   // input ring (50.7KB)
    __shared__ __align__(16) float otile[2][32 * SROW];   // output bufs (33.8KB)

    const int wsel = (blockIdx.x < 148) ? 0 : 1;          // SMSP disambiguation
    if ((threadIdx.x >> 5) != wsel) return;               // other warp exits

    const int lane = threadIdx.x & 31;
    const int seq0 = blockIdx.x * 32;
    const float* gbase = g_I + (size_t)seq0 * PITCH;

    unsigned int sb = (unsigned int)__cvta_generic_to_shared(&stile[0][0]);
    unsigned int ob = (unsigned int)__cvta_generic_to_shared(&otile[0][0]);

    // prefetch chunks 0 and 1: lane covers 16B of row r (row-major, coalesced)
    #pragma unroll
    for (int k = 0; k < 2; k++) {
        #pragma unroll
        for (int r = 0; r < 32; r++) {
            unsigned int d = sb + (unsigned int)((k * 32 * SROW + r * SROW + 4 * lane) * 4);
            const float* g = gbase + (size_t)r * PITCH + k * CHK + 4 * lane;
            CP_ASYNC16(d, g);
        }
        CP_COMMIT();
    }

    const float C1 = 70368744177664.0f;    // 2^46
    const float C2 = -70368744177664.0f;   // -2^46

    float mem = 0.0f, spf = 0.0f;
    float o0, o1, o2;

    #pragma unroll 1
    for (int k = 0; k < Tn / CHK; k++) {
        CP_WAIT1();                 // input chunk k landed
        BULK_WAIT1();               // otile[k&1] free (chunk k-2's copies done)
        __syncwarp();

        const float* st = &stile[0][0] + (k % 3) * (32 * SROW) + lane * SROW;
        float* otp = &otile[0][0] + (k & 1) * (32 * SROW) + lane * SROW;

        float4 v = *(const float4*)(st);
        #pragma unroll
        for (int i4 = 0; i4 < CHK; i4 += 4) {
            float4 vn;
            if (i4 + 4 < CHK) vn = *(const float4*)(st + i4 + 4);  // next buffer
            float q;
            // exact reference order: mem = (0.95*mem + v) - spk_prev
            q = __fadd_rn(__fmul_rn(0.95f, mem), v.x);
            mem = __fsub_rn(q, spf);
            SPIKE(spf, mem, C1, C2);
            o0 = spf;
            q = __fadd_rn(__fmul_rn(0.95f, mem), v.y);
            mem = __fsub_rn(q, spf);
            SPIKE(spf, mem, C1, C2);
            o1 = spf;
            q = __fadd_rn(__fmul_rn(0.95f, mem), v.z);
            mem = __fsub_rn(q, spf);
            SPIKE(spf, mem, C1, C2);
            o2 = spf;
            q = __fadd_rn(__fmul_rn(0.95f, mem), v.w);
            mem = __fsub_rn(q, spf);
            SPIKE(spf, mem, C1, C2);
            *(float4*)(otp + i4) = make_float4(o0, o1, o2, spf);
            v = vn;
        }

        // prefetch input chunk k+2 (row pad keeps loads in-bounds)
        #pragma unroll
        for (int r = 0; r < 32; r++) {
            unsigned int d = sb + (unsigned int)((((k + 2) % 3) * 32 * SROW
                                + r * SROW + 4 * lane) * 4);
            const float* g = gbase + (size_t)r * PITCH + (k + 2) * CHK + 4 * lane;
            CP_ASYNC16(d, g);
        }
        CP_COMMIT();

        __syncwarp();               // all lanes' STS to otile visible
        if (lane == 0) {
            FENCE_ASYNC();          // order STS -> async proxy
            #pragma unroll
            for (int r = 0; r < 32; r++) {
                float* gd = out + (size_t)(seq0 + r) * Tn + k * CHK;
                unsigned int ss = ob + (unsigned int)(((k & 1) * 32 * SROW + r * SROW) * 4);
                BULK_S2G(gd, ss, CHK * 4);
            }
            BULK_COMMIT();
        }
        __syncwarp();
    }
    BULK_WAIT0();                   // drain outstanding bulk stores
}

// ---------------------------------------------------------------------------
extern "C" void kernel_launch(void* const* d_in, const int* in_sizes, int n_in,
                              void* d_out, int out_size) {
    const float* inp = (const float*)d_in[0];   // (32,1,224,2048) f32
    const float* lw  = (const float*)d_in[1];   // (1,224) f32
    float* out = (float*)d_out;                 // (32,1,224,2048) f32

    dim3 g1(Tn / TT, Bn);
    agss_stage1<<<g1, 256>>>(inp, lw);
    agss_stage2<<<BC / 32, 64>>>(out);
}